// round 14
// baseline (speedup 1.0000x reference)
#include <cuda_runtime.h>
#include <cuda_fp16.h>
#include <cstdint>

// Problem constants
#define Bb 8
#define Tt 1024
#define Cc 1536
#define Hh 12
#define Dd 128
#define Ff 6144          // 4*C
#define BT 8192          // B*T
#define EPSF 1e-5f

// hgemm pipeline: 4 stages, K-chunk 32 (R12-proven)
#define STG_BYTES 20480
#define SMEM_BYTES (4 * STG_BYTES)   // 81920

// flash-attn smem (2-stage, V read directly in [T,D] layout)
#define FQ_ROWB 272u                  // 128 halves + pad
#define FQ_BYTES (128u * FQ_ROWB)     // 34816
#define FK_BYTES (64u * FQ_ROWB)      // 17408 (K tile: 64 rows x 256B)
#define FV_BYTES (64u * FQ_ROWB)      // 17408 (V tile: 64 rows x 256B)
#define FSTG (FK_BYTES + FV_BYTES)    // 34816
#define FSMEM (FQ_BYTES + 2u * FSTG)  // 104448 -> 2 CTAs/SM

// ---------------------------------------------------------------------------
// Scratch
// ---------------------------------------------------------------------------
__device__ __align__(256) __half g_h   [(size_t)BT * Cc];
__device__ __align__(256) __half g_qkv [(size_t)3 * BT * Cc];
__device__ __align__(256) __half g_o   [(size_t)BT * Cc];
__device__ __align__(256) __half g_f1  [(size_t)BT * Ff];
__device__ __align__(256) __half g_wqkvT[(size_t)3 * Hh * Dd * Cc];
__device__ __align__(256) __half g_woT [(size_t)Cc * Cc];
__device__ __align__(256) __half g_w1T [(size_t)Ff * Cc];
__device__ __align__(256) __half g_w2T [(size_t)Cc * Ff];
__device__ float g_x1 [(size_t)BT * Cc];
__device__ float g_x2 [(size_t)BT * Cc];
__device__ float g_f2 [(size_t)BT * Cc];

// ---------------------------------------------------------------------------
// Baseline-PTX helpers
// ---------------------------------------------------------------------------
__device__ __forceinline__ uint32_t smem_u32(const void* p) {
    uint32_t a;
    asm("{ .reg .u64 t; cvta.to.shared.u64 t, %1; cvt.u32.u64 %0, t; }" : "=r"(a) : "l"(p));
    return a;
}
__device__ __forceinline__ void cp16(uint32_t saddr, const void* gptr) {
    asm volatile("cp.async.cg.shared.global [%0], [%1], 16;" :: "r"(saddr), "l"(gptr));
}
#define CP_COMMIT() asm volatile("cp.async.commit_group;" ::: "memory")
#define CP_WAIT(n)  asm volatile("cp.async.wait_group %0;" :: "n"(n) : "memory")

__device__ __forceinline__ void ldsm4(uint32_t& r0, uint32_t& r1, uint32_t& r2,
                                      uint32_t& r3, uint32_t addr) {
    asm volatile("ldmatrix.sync.aligned.m8n8.x4.shared.b16 {%0,%1,%2,%3}, [%4];"
                 : "=r"(r0), "=r"(r1), "=r"(r2), "=r"(r3) : "r"(addr));
}
__device__ __forceinline__ void ldsm4t(uint32_t& r0, uint32_t& r1, uint32_t& r2,
                                       uint32_t& r3, uint32_t addr) {
    asm volatile("ldmatrix.sync.aligned.m8n8.x4.trans.shared.b16 {%0,%1,%2,%3}, [%4];"
                 : "=r"(r0), "=r"(r1), "=r"(r2), "=r"(r3) : "r"(addr));
}
__device__ __forceinline__ void mma_f16(float* c, const uint32_t* a, const uint32_t* b) {
    asm volatile(
        "mma.sync.aligned.m16n8k16.row.col.f32.f16.f16.f32 "
        "{%0,%1,%2,%3}, {%4,%5,%6,%7}, {%8,%9}, {%0,%1,%2,%3};"
        : "+f"(c[0]), "+f"(c[1]), "+f"(c[2]), "+f"(c[3])
        : "r"(a[0]), "r"(a[1]), "r"(a[2]), "r"(a[3]), "r"(b[0]), "r"(b[1]));
}

// ---------------------------------------------------------------------------
// fp16 NT GEMM (R12-proven): CTA 128x128, 8 warps (4Mx2N), K chunk 32, 4-stage.
// ---------------------------------------------------------------------------
__global__ __launch_bounds__(256, 2)
void hgemm(const __half* __restrict__ A, const __half* __restrict__ Bm,
           void* __restrict__ Cv, int M, int N, int K,
           int lda, int ldb, int ldc, float alpha,
           const float* __restrict__ bias, const float* __restrict__ addp,
           int doRelu, int outHalf, int zdiv,
           long long aO, long long aI, long long bO, long long bI,
           long long cO, long long cI) {
    int m0 = blockIdx.y * 128, n0 = blockIdx.x * 128;

    long long z = blockIdx.z;
    long long zo = z / zdiv, zi = z % zdiv;
    A  += zo * aO + zi * aI;
    Bm += zo * bO + zi * bI;
    size_t coff = (size_t)(zo * cO + zi * cI);
    const float* addb = addp ? addp + coff : nullptr;

    extern __shared__ __align__(16) char sm[];
    uint32_t sbase = smem_u32(sm);

    int tid = threadIdx.x, wid = tid >> 5, lane = tid & 31;
    int gid = lane >> 2, tig = lane & 3;
    int wm = (wid & 3) * 32, wn = (wid >> 2) * 64;

    int lrow = tid >> 1, lsel = tid & 1;
    const __half* aR = A + (size_t)(m0 + lrow) * lda + lsel * 16;
    const __half* bR = Bm + (size_t)(n0 + lrow) * ldb + lsel * 16;
    uint32_t dA = sbase + (uint32_t)(lrow * 80 + lsel * 32);
    uint32_t dB = dA + 10240u;

    int nch = K >> 5;
    auto issue = [&](int ch) {
        if (ch < nch) {
            uint32_t so = (uint32_t)(ch & 3) * STG_BYTES;
            int k0 = ch * 32;
            cp16(dA + so,      aR + k0);
            cp16(dA + so + 16, aR + k0 + 8);
            cp16(dB + so,      bR + k0);
            cp16(dB + so + 16, bR + k0 + 8);
        }
        CP_COMMIT();
    };

    int g8 = lane >> 3, l8 = lane & 7;
    uint32_t aoff = (uint32_t)((((g8 & 1) * 8 + l8) * 80) + (g8 >> 1) * 16);
    uint32_t boff = 10240u + (uint32_t)((((g8 >> 1) * 8 + l8) * 80) + (g8 & 1) * 16);

    float acc[2][8][4];
    #pragma unroll
    for (int i = 0; i < 2; i++)
        #pragma unroll
        for (int j = 0; j < 8; j++)
            #pragma unroll
            for (int r = 0; r < 4; r++) acc[i][j][r] = 0.f;

    issue(0); issue(1); issue(2);

    for (int ch = 0; ch < nch; ch++) {
        CP_WAIT(2);
        __syncthreads();
        issue(ch + 3);

        uint32_t stg = sbase + (uint32_t)(ch & 3) * STG_BYTES;
        uint32_t aw0 = stg + aoff + (uint32_t)(wm * 80);
        uint32_t aw1 = aw0 + 16u * 80u;
        uint32_t bw  = stg + boff + (uint32_t)(wn * 80);

        #pragma unroll
        for (int s = 0; s < 2; s++) {
            uint32_t a[2][4];
            ldsm4(a[0][0], a[0][1], a[0][2], a[0][3], aw0 + s * 32);
            ldsm4(a[1][0], a[1][1], a[1][2], a[1][3], aw1 + s * 32);
            uint32_t b[8][2];
            #pragma unroll
            for (int jj = 0; jj < 4; jj++) {
                uint32_t t0, t1, t2, t3;
                ldsm4(t0, t1, t2, t3, bw + (uint32_t)(jj * 16 * 80) + s * 32);
                b[2 * jj][0] = t0; b[2 * jj][1] = t1;
                b[2 * jj + 1][0] = t2; b[2 * jj + 1][1] = t3;
            }
            #pragma unroll
            for (int i = 0; i < 2; i++)
                #pragma unroll
                for (int j = 0; j < 8; j++)
                    mma_f16(acc[i][j], a[i], b[j]);
        }
    }

    #pragma unroll
    for (int i = 0; i < 2; i++) {
        #pragma unroll
        for (int j = 0; j < 8; j++) {
            int r0 = m0 + wm + i * 16 + gid;
            int c  = n0 + wn + j * 8 + 2 * tig;
            #pragma unroll
            for (int hh = 0; hh < 2; hh++) {
                int r = r0 + hh * 8;
                float v0 = acc[i][j][2 * hh + 0] * alpha;
                float v1 = acc[i][j][2 * hh + 1] * alpha;
                if (bias) { v0 += bias[c]; v1 += bias[c + 1]; }
                if (doRelu) { v0 = fmaxf(v0, 0.f); v1 = fmaxf(v1, 0.f); }
                if (addb) {
                    const float* ap = addb + (size_t)r * ldc + c;
                    v0 += ap[0]; v1 += ap[1];
                }
                if (outHalf) {
                    __half2* cp = (__half2*)((__half*)Cv + coff + (size_t)r * ldc + c);
                    *cp = __floats2half2_rn(v0, v1);
                } else {
                    float2* cp = (float2*)((float*)Cv + coff + (size_t)r * ldc + c);
                    *cp = make_float2(v0, v1);
                }
            }
        }
    }
}

// ---------------------------------------------------------------------------
// Fused flash attention: V read directly from [B,T,C] via trans-ldmatrix.
// 2-stage pipeline, 2 CTAs/SM, heavy tiles first.
// ---------------------------------------------------------------------------
__global__ __launch_bounds__(256, 2)
void flash_attn(const __half* __restrict__ qg, const __half* __restrict__ kg,
                const __half* __restrict__ vg, __half* __restrict__ og) {
    extern __shared__ __align__(16) char sm[];
    uint32_t sb = smem_u32(sm);
    int qt = gridDim.x - 1 - blockIdx.x;    // heavy (large-qt) tiles first
    int z = blockIdx.y;
    int bi = z / Hh, hi = z % Hh;
    const __half* qb = qg + (size_t)bi * Tt * Cc + hi * Dd;
    const __half* kb = kg + (size_t)bi * Tt * Cc + hi * Dd;
    const __half* vb = vg + (size_t)bi * Tt * Cc + hi * Dd;
    __half* ob = og + (size_t)bi * Tt * Cc + hi * Dd;

    int tid = threadIdx.x, wid = tid >> 5, lane = tid & 31;
    int gid = lane >> 2, tig = lane & 3;
    int g8 = lane >> 3, l8 = lane & 7;
    int wr = wid * 16;
    int nkt = 2 * qt + 2;

    // Q tile once (bundled into first commit group)
    #pragma unroll
    for (int i = 0; i < 8; i++) {
        int c = tid + i * 256;
        int r = c >> 4, q16 = c & 15;
        cp16(sb + (uint32_t)r * FQ_ROWB + (uint32_t)q16 * 16,
             qb + (size_t)(qt * 128 + r) * Cc + q16 * 8);
    }
    auto issueKV = [&](int kt) {
        if (kt < nkt) {
            uint32_t so = sb + FQ_BYTES + (uint32_t)(kt & 1) * FSTG;
            #pragma unroll
            for (int i = 0; i < 4; i++) {           // K: 64 rows x 256B
                int c = tid + i * 256;
                int r = c >> 4, q16 = c & 15;
                cp16(so + (uint32_t)r * FQ_ROWB + (uint32_t)q16 * 16,
                     kb + (size_t)(kt * 64 + r) * Cc + q16 * 8);
            }
            #pragma unroll
            for (int i = 0; i < 4; i++) {           // V: 64 rows x 256B ([T,D])
                int c = tid + i * 256;
                int r = c >> 4, q16 = c & 15;
                cp16(so + FK_BYTES + (uint32_t)r * FQ_ROWB + (uint32_t)q16 * 16,
                     vb + (size_t)(kt * 64 + r) * Cc + q16 * 8);
            }
        }
        CP_COMMIT();
    };

    issueKV(0); issueKV(1);

    uint32_t qoff = sb + (uint32_t)((wr + (g8 & 1) * 8 + l8) * FQ_ROWB) + (uint32_t)(g8 >> 1) * 16;
    uint32_t koffB = (uint32_t)((((g8 >> 1) * 8 + l8)) * FQ_ROWB) + (uint32_t)(g8 & 1) * 16;
    // trans-ldsm V offset: row = k(t)-part, col = n(d)-part
    uint32_t voffB = (uint32_t)(((g8 & 1) * 8 + l8)) * FQ_ROWB + (uint32_t)((g8 >> 1) * 16);

    float Oa[16][4];
    #pragma unroll
    for (int j = 0; j < 16; j++)
        #pragma unroll
        for (int r = 0; r < 4; r++) Oa[j][r] = 0.f;
    float m0v = -1e30f, m1v = -1e30f, l0 = 0.f, l1 = 0.f;

    int grow0 = qt * 128 + wr + gid;
    int grow1 = grow0 + 8;
    const float ALPHA = 0.08838834764831843f;

    for (int kt = 0; kt < nkt; kt++) {
        CP_WAIT(1);
        __syncthreads();

        uint32_t stg = sb + FQ_BYTES + (uint32_t)(kt & 1) * FSTG;

        // S = Q K^T for this 64-col tile
        float S[8][4];
        #pragma unroll
        for (int j = 0; j < 8; j++) { S[j][0] = S[j][1] = S[j][2] = S[j][3] = 0.f; }
        #pragma unroll
        for (int ks = 0; ks < 8; ks++) {
            uint32_t aq[4];
            ldsm4(aq[0], aq[1], aq[2], aq[3], qoff + (uint32_t)ks * 32);
            uint32_t bk[8][2];
            #pragma unroll
            for (int jp = 0; jp < 4; jp++) {
                uint32_t t0, t1, t2, t3;
                ldsm4(t0, t1, t2, t3,
                      stg + koffB + (uint32_t)(jp * 16) * FQ_ROWB + (uint32_t)ks * 32);
                bk[2 * jp][0] = t0; bk[2 * jp][1] = t1;
                bk[2 * jp + 1][0] = t2; bk[2 * jp + 1][1] = t3;
            }
            #pragma unroll
            for (int j = 0; j < 8; j++) mma_f16(S[j], aq, bk[j]);
        }

        // mask + scale + online softmax
        int cbase = kt * 64;
        float mt0 = -1e30f, mt1 = -1e30f;
        #pragma unroll
        for (int j = 0; j < 8; j++) {
            int c0 = cbase + j * 8 + 2 * tig, c1 = c0 + 1;
            S[j][0] = (c0 <= grow0) ? S[j][0] * ALPHA : -1e30f;
            S[j][1] = (c1 <= grow0) ? S[j][1] * ALPHA : -1e30f;
            S[j][2] = (c0 <= grow1) ? S[j][2] * ALPHA : -1e30f;
            S[j][3] = (c1 <= grow1) ? S[j][3] * ALPHA : -1e30f;
            mt0 = fmaxf(mt0, fmaxf(S[j][0], S[j][1]));
            mt1 = fmaxf(mt1, fmaxf(S[j][2], S[j][3]));
        }
        mt0 = fmaxf(mt0, __shfl_xor_sync(0xffffffffu, mt0, 1));
        mt0 = fmaxf(mt0, __shfl_xor_sync(0xffffffffu, mt0, 2));
        mt1 = fmaxf(mt1, __shfl_xor_sync(0xffffffffu, mt1, 1));
        mt1 = fmaxf(mt1, __shfl_xor_sync(0xffffffffu, mt1, 2));
        float mn0 = fmaxf(m0v, mt0), mn1 = fmaxf(m1v, mt1);
        float f0 = __expf(m0v - mn0), f1 = __expf(m1v - mn1);
        m0v = mn0; m1v = mn1;
        float ps0 = 0.f, ps1 = 0.f;
        #pragma unroll
        for (int j = 0; j < 8; j++) {
            S[j][0] = __expf(S[j][0] - m0v);
            S[j][1] = __expf(S[j][1] - m0v);
            S[j][2] = __expf(S[j][2] - m1v);
            S[j][3] = __expf(S[j][3] - m1v);
            ps0 += S[j][0] + S[j][1];
            ps1 += S[j][2] + S[j][3];
        }
        ps0 += __shfl_xor_sync(0xffffffffu, ps0, 1);
        ps0 += __shfl_xor_sync(0xffffffffu, ps0, 2);
        ps1 += __shfl_xor_sync(0xffffffffu, ps1, 1);
        ps1 += __shfl_xor_sync(0xffffffffu, ps1, 2);
        l0 = l0 * f0 + ps0;
        l1 = l1 * f1 + ps1;
        #pragma unroll
        for (int j = 0; j < 16; j++) {
            Oa[j][0] *= f0; Oa[j][1] *= f0; Oa[j][2] *= f1; Oa[j][3] *= f1;
        }

        // O += P V : P (regs) x V tile (trans-ldmatrix on [t][d] rows)
        #pragma unroll
        for (int jj = 0; jj < 4; jj++) {
            uint32_t aP[4];
            __half2 p0 = __floats2half2_rn(S[2 * jj][0], S[2 * jj][1]);
            __half2 p1 = __floats2half2_rn(S[2 * jj][2], S[2 * jj][3]);
            __half2 p2 = __floats2half2_rn(S[2 * jj + 1][0], S[2 * jj + 1][1]);
            __half2 p3 = __floats2half2_rn(S[2 * jj + 1][2], S[2 * jj + 1][3]);
            aP[0] = *(uint32_t*)&p0; aP[1] = *(uint32_t*)&p1;
            aP[2] = *(uint32_t*)&p2; aP[3] = *(uint32_t*)&p3;
            uint32_t bv[16][2];
            #pragma unroll
            for (int jp = 0; jp < 8; jp++) {
                uint32_t t0, t1, t2, t3;
                ldsm4t(t0, t1, t2, t3,
                       stg + FK_BYTES + voffB + (uint32_t)(jj * 16) * FQ_ROWB + (uint32_t)(jp * 32));
                bv[2 * jp][0] = t0; bv[2 * jp][1] = t1;
                bv[2 * jp + 1][0] = t2; bv[2 * jp + 1][1] = t3;
            }
            #pragma unroll
            for (int dt = 0; dt < 16; dt++) mma_f16(Oa[dt], aP, bv[dt]);
        }

        __syncthreads();          // all warps done with stage (kt&1)
        issueKV(kt + 2);          // refill same buffer
    }

    float il0 = 1.f / l0, il1 = 1.f / l1;
    #pragma unroll
    for (int dt = 0; dt < 16; dt++) {
        int d = dt * 8 + 2 * tig;
        *(__half2*)(ob + (size_t)grow0 * Cc + d) = __floats2half2_rn(Oa[dt][0] * il0, Oa[dt][1] * il0);
        *(__half2*)(ob + (size_t)grow1 * Cc + d) = __floats2half2_rn(Oa[dt][2] * il1, Oa[dt][3] * il1);
    }
}

// ---------------------------------------------------------------------------
// Tiled transpose (fp32 -> fp16)
// ---------------------------------------------------------------------------
__global__ void transpose_f2h(const float* __restrict__ in, __half* __restrict__ out,
                              int ldi, int ldo, int zdiv,
                              long long iO, long long iI, long long oO, long long oI) {
    __shared__ float tile[32][33];
    long long z = blockIdx.z;
    in  += (z / zdiv) * iO + (z % zdiv) * iI;
    out += (z / zdiv) * oO + (z % zdiv) * oI;
    int r0 = blockIdx.y * 32, c0 = blockIdx.x * 32;
    int tx = threadIdx.x & 31, ty = threadIdx.x >> 5;
    #pragma unroll
    for (int i = ty; i < 32; i += 8)
        tile[i][tx] = in[(size_t)(r0 + i) * ldi + c0 + tx];
    __syncthreads();
    #pragma unroll
    for (int i = ty; i < 32; i += 8)
        out[(size_t)(c0 + i) * ldo + r0 + tx] = __float2half_rn(tile[tx][i]);
}

// ---------------------------------------------------------------------------
// Paired block reduction (two sums, one barrier tree)
// ---------------------------------------------------------------------------
__device__ __forceinline__ void blk_reduce_sum2(float& a, float& b) {
    __shared__ float2 sh[32];
    __syncthreads();
    int lane = threadIdx.x & 31, w = threadIdx.x >> 5;
    #pragma unroll
    for (int o = 16; o > 0; o >>= 1) {
        a += __shfl_down_sync(0xffffffffu, a, o);
        b += __shfl_down_sync(0xffffffffu, b, o);
    }
    if (lane == 0) sh[w] = make_float2(a, b);
    __syncthreads();
    int nw = blockDim.x >> 5;
    if (w == 0) {
        float2 v = (lane < nw) ? sh[lane] : make_float2(0.f, 0.f);
        a = v.x; b = v.y;
        #pragma unroll
        for (int o = 16; o > 0; o >>= 1) {
            a += __shfl_down_sync(0xffffffffu, a, o);
            b += __shfl_down_sync(0xffffffffu, b, o);
        }
        if (lane == 0) sh[0] = make_float2(a, b);
    }
    __syncthreads();
    float2 r = sh[0];
    a = r.x; b = r.y;
}

// ---------------------------------------------------------------------------
// LayerNorm: register-cached, float2 vectorized
// ---------------------------------------------------------------------------
__global__ void ln_kernel(const float* __restrict__ x, const float* __restrict__ g,
                          const float* __restrict__ b, __half* __restrict__ out) {
    size_t row = blockIdx.x;
    const float2* xr = (const float2*)(x + row * Cc);
    float2 xv[3];
    float s = 0.f, s2 = 0.f;
    #pragma unroll
    for (int j = 0; j < 3; j++) {
        xv[j] = xr[threadIdx.x + j * 256];
        s += xv[j].x + xv[j].y;
        s2 += xv[j].x * xv[j].x + xv[j].y * xv[j].y;
    }
    blk_reduce_sum2(s, s2);
    float mean = s * (1.0f / Cc);
    float var = s2 * (1.0f / Cc) - mean * mean;
    float inv = rsqrtf(var + EPSF);
    __half2* orow = (__half2*)(out + row * Cc);
    const float2* g2 = (const float2*)g;
    const float2* b2 = (const float2*)b;
    #pragma unroll
    for (int j = 0; j < 3; j++) {
        int idx = threadIdx.x + j * 256;
        float2 gg = g2[idx], bb = b2[idx];
        orow[idx] = __floats2half2_rn((xv[j].x - mean) * inv * gg.x + bb.x,
                                      (xv[j].y - mean) * inv * gg.y + bb.y);
    }
}

// ---------------------------------------------------------------------------
// Fused BN1 + LN2: register-cached, single x1 read
// ---------------------------------------------------------------------------
__global__ void bn_ln_kernel(const float* __restrict__ x1,
                             const float* __restrict__ bng, const float* __restrict__ bnb,
                             const float* __restrict__ lng, const float* __restrict__ lnb,
                             float* __restrict__ x2, __half* __restrict__ h) {
    int t = blockIdx.x;
    float2 xv[Bb][3];
    float s = 0.f, s2 = 0.f;
    #pragma unroll
    for (int bi = 0; bi < Bb; bi++) {
        const float2* xr = (const float2*)(x1 + ((size_t)bi * Tt + t) * Cc);
        #pragma unroll
        for (int j = 0; j < 3; j++) {
            xv[bi][j] = xr[threadIdx.x + j * 256];
            s += xv[bi][j].x + xv[bi][j].y;
            s2 += xv[bi][j].x * xv[bi][j].x + xv[bi][j].y * xv[bi][j].y;
        }
    }
    const float cnt = (float)(Bb * Cc);
    blk_reduce_sum2(s, s2);
    float mean = s / cnt;
    float var = s2 / cnt - mean * mean;
    float inv = rsqrtf(var + EPSF);
    float gg = bng[t], bv = bnb[t];

    const float2* lg2 = (const float2*)lng;
    const float2* lb2 = (const float2*)lnb;
    #pragma unroll
    for (int bi = 0; bi < Bb; bi++) {
        float2* x2r = (float2*)(x2 + ((size_t)bi * Tt + t) * Cc);
        __half2* hr = (__half2*)(h + ((size_t)bi * Tt + t) * Cc);
        float ls = 0.f, ls2 = 0.f;
        #pragma unroll
        for (int j = 0; j < 3; j++) {
            float yx = (xv[bi][j].x - mean) * inv * gg + bv;
            float yy = (xv[bi][j].y - mean) * inv * gg + bv;
            xv[bi][j] = make_float2(yx, yy);
            x2r[threadIdx.x + j * 256] = xv[bi][j];
            ls += yx + yy; ls2 += yx * yx + yy * yy;
        }
        blk_reduce_sum2(ls, ls2);
        float lm = ls * (1.0f / Cc);
        float lvar = ls2 * (1.0f / Cc) - lm * lm;
        float linv = rsqrtf(lvar + EPSF);
        #pragma unroll
        for (int j = 0; j < 3; j++) {
            int idx = threadIdx.x + j * 256;
            float2 lg = lg2[idx], lb = lb2[idx];
            hr[idx] = __floats2half2_rn((xv[bi][j].x - lm) * linv * lg.x + lb.x,
                                        (xv[bi][j].y - lm) * linv * lg.y + lb.y);
        }
    }
}

// ---------------------------------------------------------------------------
// Final BatchNorm: register-cached, single read
// ---------------------------------------------------------------------------
__global__ void bn_kernel(const float* __restrict__ x, const float* __restrict__ g,
                          const float* __restrict__ bb, float* __restrict__ out) {
    int t = blockIdx.x;
    float2 xv[Bb][3];
    float s = 0.f, s2 = 0.f;
    #pragma unroll
    for (int bi = 0; bi < Bb; bi++) {
        const float2* xr = (const float2*)(x + ((size_t)bi * Tt + t) * Cc);
        #pragma unroll
        for (int j = 0; j < 3; j++) {
            xv[bi][j] = xr[threadIdx.x + j * 256];
            s += xv[bi][j].x + xv[bi][j].y;
            s2 += xv[bi][j].x * xv[bi][j].x + xv[bi][j].y * xv[bi][j].y;
        }
    }
    const float cnt = (float)(Bb * Cc);
    blk_reduce_sum2(s, s2);
    float mean = s / cnt;
    float var = s2 / cnt - mean * mean;
    float inv = rsqrtf(var + EPSF);
    float gg = g[t], bv = bb[t];
    #pragma unroll
    for (int bi = 0; bi < Bb; bi++) {
        float2* orow = (float2*)(out + ((size_t)bi * Tt + t) * Cc);
        #pragma unroll
        for (int j = 0; j < 3; j++)
            orow[threadIdx.x + j * 256] =
                make_float2((xv[bi][j].x - mean) * inv * gg + bv,
                            (xv[bi][j].y - mean) * inv * gg + bv);
    }
}

// ---------------------------------------------------------------------------
// Launch
// ---------------------------------------------------------------------------
extern "C" void kernel_launch(void* const* d_in, const int* in_sizes, int n_in,
                              void* d_out, int out_size) {
    const float* x     = (const float*)d_in[0];
    const float* wq    = (const float*)d_in[1];
    const float* wk    = (const float*)d_in[2];
    const float* wv    = (const float*)d_in[3];
    const float* wo    = (const float*)d_in[4];
    const float* bo    = (const float*)d_in[5];
    const float* ln1_g = (const float*)d_in[6];
    const float* ln1_b = (const float*)d_in[7];
    const float* ln2_g = (const float*)d_in[8];
    const float* ln2_b = (const float*)d_in[9];
    const float* w1    = (const float*)d_in[10];
    const float* b1    = (const float*)d_in[11];
    const float* w2    = (const float*)d_in[12];
    const float* b2    = (const float*)d_in[13];
    const float* bn1_g = (const float*)d_in[14];
    const float* bn1_b = (const float*)d_in[15];
    const float* bn2_g = (const float*)d_in[16];
    const float* bn2_b = (const float*)d_in[17];
    float* out = (float*)d_out;

    __half *h, *qkv, *o, *f1, *wqkvT, *woT, *w1T, *w2T;
    float *x1, *x2, *f2;
    cudaGetSymbolAddress((void**)&h,   g_h);
    cudaGetSymbolAddress((void**)&qkv, g_qkv);
    cudaGetSymbolAddress((void**)&o,   g_o);
    cudaGetSymbolAddress((void**)&f1,  g_f1);
    cudaGetSymbolAddress((void**)&wqkvT, g_wqkvT);
    cudaGetSymbolAddress((void**)&woT, g_woT);
    cudaGetSymbolAddress((void**)&w1T, g_w1T);
    cudaGetSymbolAddress((void**)&w2T, g_w2T);
    cudaGetSymbolAddress((void**)&x1, g_x1);
    cudaGetSymbolAddress((void**)&x2, g_x2);
    cudaGetSymbolAddress((void**)&f2, g_f2);

    const long long CD = (long long)Cc * Dd;
    const long long HDC = (long long)Hh * Dd * Cc;

    const __half* q = qkv;
    const __half* k = qkv + (size_t)BT * Cc;
    const __half* v = qkv + (size_t)2 * BT * Cc;

    cudaFuncSetAttribute(hgemm, cudaFuncAttributeMaxDynamicSharedMemorySize, SMEM_BYTES);
    cudaFuncSetAttribute(flash_attn, cudaFuncAttributeMaxDynamicSharedMemorySize, FSMEM);

    transpose_f2h<<<dim3(Dd / 32, Cc / 32, Hh), 256>>>(wq, wqkvT,           Dd, Cc, 1, CD, 0, CD, 0);
    transpose_f2h<<<dim3(Dd / 32, Cc / 32, Hh), 256>>>(wk, wqkvT + HDC,     Dd, Cc, 1, CD, 0, CD, 0);
    transpose_f2h<<<dim3(Dd / 32, Cc / 32, Hh), 256>>>(wv, wqkvT + 2 * HDC, Dd, Cc, 1, CD, 0, CD, 0);
    ln_kernel<<<BT, 256>>>(x, ln1_g, ln1_b, h);
    transpose_f2h<<<dim3(Cc / 32, Cc / 32, 1), 256>>>(wo, woT, Cc, Cc, 1, 0, 0, 0, 0);

    // QKV fused: z = which*Hh + head
    {
        dim3 g(1, BT / 128, 3 * Hh);
        hgemm<<<g, 256, SMEM_BYTES>>>(h, wqkvT, (void*)qkv, BT, Dd, Cc, Cc, Cc, Cc, 1.f,
                                      nullptr, nullptr, 0, 1, Hh,
                                      0, 0, HDC, CD, (long long)BT * Cc, (long long)Dd);
    }

    transpose_f2h<<<dim3(Ff / 32, Cc / 32, 1), 256>>>(w1, w1T, Ff, Cc, 1, 0, 0, 0, 0);
    transpose_f2h<<<dim3(Cc / 32, Ff / 32, 1), 256>>>(w2, w2T, Cc, Ff, 1, 0, 0, 0, 0);

    // fused causal attention (V read directly)
    flash_attn<<<dim3(Tt / 128, Bb * Hh), 256, FSMEM>>>(q, k, v, o);

    // x1 = x + (O @ wo + bo)
    {
        dim3 g(Cc / 128, BT / 128, 1);
        hgemm<<<g, 256, SMEM_BYTES>>>(o, woT, x1, BT, Cc, Cc, Cc, Cc, Cc, 1.f,
                                      bo, x, 0, 0, 1, 0, 0, 0, 0, 0, 0);
    }

    // BN1 + LN2 fused
    bn_ln_kernel<<<Tt, 256>>>(x1, bn1_g, bn1_b, ln2_g, ln2_b, x2, h);

    // f1 = relu(h @ w1 + b1)
    {
        dim3 g(Ff / 128, BT / 128, 1);
        hgemm<<<g, 256, SMEM_BYTES>>>(h, w1T, (void*)f1, BT, Ff, Cc, Cc, Cc, Ff, 1.f,
                                      b1, nullptr, 1, 1, 1, 0, 0, 0, 0, 0, 0);
    }

    // f2 = x2 + (f1 @ w2 + b2)
    {
        dim3 g(Cc / 128, BT / 128, 1);
        hgemm<<<g, 256, SMEM_BYTES>>>(f1, w2T, f2, BT, Cc, Ff, Ff, Ff, Cc, 1.f,
                                      b2, x2, 0, 0, 1, 0, 0, 0, 0, 0, 0);
    }

    // bn2 -> out
    bn_kernel<<<Tt, 256>>>(f2, bn2_g, bn2_b, out);
}

// round 15
// speedup vs baseline: 1.5385x; 1.5385x over previous
#include <cuda_runtime.h>
#include <cuda_fp16.h>
#include <cstdint>

// Problem constants
#define Bb 8
#define Tt 1024
#define Cc 1536
#define Hh 12
#define Dd 128
#define Ff 6144          // 4*C
#define BT 8192          // B*T
#define EPSF 1e-5f

// hgemm pipeline: 4 stages, K-chunk 32 (R12-proven)
#define STG_BYTES 20480
#define SMEM_BYTES (4 * STG_BYTES)   // 81920

// flash-attn smem (2-stage, V read directly in [T,D] layout)
#define FQ_ROWB 272u                  // 128 halves + pad
#define FQ_BYTES (128u * FQ_ROWB)     // 34816
#define FK_BYTES (64u * FQ_ROWB)      // 17408 (K tile: 64 rows x 256B)
#define FV_BYTES (64u * FQ_ROWB)      // 17408 (V tile: 64 rows x 256B)
#define FSTG (FK_BYTES + FV_BYTES)    // 34816
#define FSMEM (FQ_BYTES + 2u * FSTG)  // 104448 -> 2 CTAs/SM

// ---------------------------------------------------------------------------
// Scratch
// ---------------------------------------------------------------------------
__device__ __align__(256) __half g_h   [(size_t)BT * Cc];
__device__ __align__(256) __half g_qkv [(size_t)3 * BT * Cc];
__device__ __align__(256) __half g_o   [(size_t)BT * Cc];
__device__ __align__(256) __half g_f1  [(size_t)BT * Ff];
__device__ __align__(256) __half g_wqkvT[(size_t)3 * Hh * Dd * Cc];
__device__ __align__(256) __half g_woT [(size_t)Cc * Cc];
__device__ __align__(256) __half g_w1T [(size_t)Ff * Cc];
__device__ __align__(256) __half g_w2T [(size_t)Cc * Ff];
__device__ float g_x1 [(size_t)BT * Cc];
__device__ float g_x2 [(size_t)BT * Cc];
__device__ float g_f2 [(size_t)BT * Cc];

// ---------------------------------------------------------------------------
// Baseline-PTX helpers
// ---------------------------------------------------------------------------
__device__ __forceinline__ uint32_t smem_u32(const void* p) {
    uint32_t a;
    asm("{ .reg .u64 t; cvta.to.shared.u64 t, %1; cvt.u32.u64 %0, t; }" : "=r"(a) : "l"(p));
    return a;
}
__device__ __forceinline__ void cp16(uint32_t saddr, const void* gptr) {
    asm volatile("cp.async.cg.shared.global [%0], [%1], 16;" :: "r"(saddr), "l"(gptr));
}
#define CP_COMMIT() asm volatile("cp.async.commit_group;" ::: "memory")
#define CP_WAIT(n)  asm volatile("cp.async.wait_group %0;" :: "n"(n) : "memory")

__device__ __forceinline__ void ldsm4(uint32_t& r0, uint32_t& r1, uint32_t& r2,
                                      uint32_t& r3, uint32_t addr) {
    asm volatile("ldmatrix.sync.aligned.m8n8.x4.shared.b16 {%0,%1,%2,%3}, [%4];"
                 : "=r"(r0), "=r"(r1), "=r"(r2), "=r"(r3) : "r"(addr));
}
__device__ __forceinline__ void ldsm4t(uint32_t& r0, uint32_t& r1, uint32_t& r2,
                                       uint32_t& r3, uint32_t addr) {
    asm volatile("ldmatrix.sync.aligned.m8n8.x4.trans.shared.b16 {%0,%1,%2,%3}, [%4];"
                 : "=r"(r0), "=r"(r1), "=r"(r2), "=r"(r3) : "r"(addr));
}
__device__ __forceinline__ void mma_f16(float* c, const uint32_t* a, const uint32_t* b) {
    asm volatile(
        "mma.sync.aligned.m16n8k16.row.col.f32.f16.f16.f32 "
        "{%0,%1,%2,%3}, {%4,%5,%6,%7}, {%8,%9}, {%0,%1,%2,%3};"
        : "+f"(c[0]), "+f"(c[1]), "+f"(c[2]), "+f"(c[3])
        : "r"(a[0]), "r"(a[1]), "r"(a[2]), "r"(a[3]), "r"(b[0]), "r"(b[1]));
}

// ---------------------------------------------------------------------------
// fp16 NT GEMM (R12-proven): CTA 128x128, 8 warps (4Mx2N), K chunk 32, 4-stage.
// ---------------------------------------------------------------------------
__global__ __launch_bounds__(256, 2)
void hgemm(const __half* __restrict__ A, const __half* __restrict__ Bm,
           void* __restrict__ Cv, int M, int N, int K,
           int lda, int ldb, int ldc, float alpha,
           const float* __restrict__ bias, const float* __restrict__ addp,
           int doRelu, int outHalf, int zdiv,
           long long aO, long long aI, long long bO, long long bI,
           long long cO, long long cI) {
    int m0 = blockIdx.y * 128, n0 = blockIdx.x * 128;

    long long z = blockIdx.z;
    long long zo = z / zdiv, zi = z % zdiv;
    A  += zo * aO + zi * aI;
    Bm += zo * bO + zi * bI;
    size_t coff = (size_t)(zo * cO + zi * cI);
    const float* addb = addp ? addp + coff : nullptr;

    extern __shared__ __align__(16) char sm[];
    uint32_t sbase = smem_u32(sm);

    int tid = threadIdx.x, wid = tid >> 5, lane = tid & 31;
    int gid = lane >> 2, tig = lane & 3;
    int wm = (wid & 3) * 32, wn = (wid >> 2) * 64;

    int lrow = tid >> 1, lsel = tid & 1;
    const __half* aR = A + (size_t)(m0 + lrow) * lda + lsel * 16;
    const __half* bR = Bm + (size_t)(n0 + lrow) * ldb + lsel * 16;
    uint32_t dA = sbase + (uint32_t)(lrow * 80 + lsel * 32);
    uint32_t dB = dA + 10240u;

    int nch = K >> 5;
    auto issue = [&](int ch) {
        if (ch < nch) {
            uint32_t so = (uint32_t)(ch & 3) * STG_BYTES;
            int k0 = ch * 32;
            cp16(dA + so,      aR + k0);
            cp16(dA + so + 16, aR + k0 + 8);
            cp16(dB + so,      bR + k0);
            cp16(dB + so + 16, bR + k0 + 8);
        }
        CP_COMMIT();
    };

    int g8 = lane >> 3, l8 = lane & 7;
    uint32_t aoff = (uint32_t)((((g8 & 1) * 8 + l8) * 80) + (g8 >> 1) * 16);
    uint32_t boff = 10240u + (uint32_t)((((g8 >> 1) * 8 + l8) * 80) + (g8 & 1) * 16);

    float acc[2][8][4];
    #pragma unroll
    for (int i = 0; i < 2; i++)
        #pragma unroll
        for (int j = 0; j < 8; j++)
            #pragma unroll
            for (int r = 0; r < 4; r++) acc[i][j][r] = 0.f;

    issue(0); issue(1); issue(2);

    for (int ch = 0; ch < nch; ch++) {
        CP_WAIT(2);
        __syncthreads();
        issue(ch + 3);

        uint32_t stg = sbase + (uint32_t)(ch & 3) * STG_BYTES;
        uint32_t aw0 = stg + aoff + (uint32_t)(wm * 80);
        uint32_t aw1 = aw0 + 16u * 80u;
        uint32_t bw  = stg + boff + (uint32_t)(wn * 80);

        #pragma unroll
        for (int s = 0; s < 2; s++) {
            uint32_t a[2][4];
            ldsm4(a[0][0], a[0][1], a[0][2], a[0][3], aw0 + s * 32);
            ldsm4(a[1][0], a[1][1], a[1][2], a[1][3], aw1 + s * 32);
            uint32_t b[8][2];
            #pragma unroll
            for (int jj = 0; jj < 4; jj++) {
                uint32_t t0, t1, t2, t3;
                ldsm4(t0, t1, t2, t3, bw + (uint32_t)(jj * 16 * 80) + s * 32);
                b[2 * jj][0] = t0; b[2 * jj][1] = t1;
                b[2 * jj + 1][0] = t2; b[2 * jj + 1][1] = t3;
            }
            #pragma unroll
            for (int i = 0; i < 2; i++)
                #pragma unroll
                for (int j = 0; j < 8; j++)
                    mma_f16(acc[i][j], a[i], b[j]);
        }
    }

    #pragma unroll
    for (int i = 0; i < 2; i++) {
        #pragma unroll
        for (int j = 0; j < 8; j++) {
            int r0 = m0 + wm + i * 16 + gid;
            int c  = n0 + wn + j * 8 + 2 * tig;
            #pragma unroll
            for (int hh = 0; hh < 2; hh++) {
                int r = r0 + hh * 8;
                float v0 = acc[i][j][2 * hh + 0] * alpha;
                float v1 = acc[i][j][2 * hh + 1] * alpha;
                if (bias) { v0 += bias[c]; v1 += bias[c + 1]; }
                if (doRelu) { v0 = fmaxf(v0, 0.f); v1 = fmaxf(v1, 0.f); }
                if (addb) {
                    const float* ap = addb + (size_t)r * ldc + c;
                    v0 += ap[0]; v1 += ap[1];
                }
                if (outHalf) {
                    __half2* cp = (__half2*)((__half*)Cv + coff + (size_t)r * ldc + c);
                    *cp = __floats2half2_rn(v0, v1);
                } else {
                    float2* cp = (float2*)((float*)Cv + coff + (size_t)r * ldc + c);
                    *cp = make_float2(v0, v1);
                }
            }
        }
    }
}

// ---------------------------------------------------------------------------
// Fused flash attention: V read directly from [B,T,C] via trans-ldmatrix.
// 2-stage pipeline, 2 CTAs/SM, heavy tiles first.
// ---------------------------------------------------------------------------
__global__ __launch_bounds__(256, 2)
void flash_attn(const __half* __restrict__ qg, const __half* __restrict__ kg,
                const __half* __restrict__ vg, __half* __restrict__ og) {
    extern __shared__ __align__(16) char sm[];
    uint32_t sb = smem_u32(sm);
    int qt = gridDim.x - 1 - blockIdx.x;    // heavy (large-qt) tiles first
    int z = blockIdx.y;
    int bi = z / Hh, hi = z % Hh;
    const __half* qb = qg + (size_t)bi * Tt * Cc + hi * Dd;
    const __half* kb = kg + (size_t)bi * Tt * Cc + hi * Dd;
    const __half* vb = vg + (size_t)bi * Tt * Cc + hi * Dd;
    __half* ob = og + (size_t)bi * Tt * Cc + hi * Dd;

    int tid = threadIdx.x, wid = tid >> 5, lane = tid & 31;
    int gid = lane >> 2, tig = lane & 3;
    int g8 = lane >> 3, l8 = lane & 7;
    int wr = wid * 16;
    int nkt = 2 * qt + 2;

    // Q tile once (bundled into first commit group)
    #pragma unroll
    for (int i = 0; i < 8; i++) {
        int c = tid + i * 256;
        int r = c >> 4, q16 = c & 15;
        cp16(sb + (uint32_t)r * FQ_ROWB + (uint32_t)q16 * 16,
             qb + (size_t)(qt * 128 + r) * Cc + q16 * 8);
    }
    auto issueKV = [&](int kt) {
        if (kt < nkt) {
            uint32_t so = sb + FQ_BYTES + (uint32_t)(kt & 1) * FSTG;
            #pragma unroll
            for (int i = 0; i < 4; i++) {           // K: 64 rows x 256B
                int c = tid + i * 256;
                int r = c >> 4, q16 = c & 15;
                cp16(so + (uint32_t)r * FQ_ROWB + (uint32_t)q16 * 16,
                     kb + (size_t)(kt * 64 + r) * Cc + q16 * 8);
            }
            #pragma unroll
            for (int i = 0; i < 4; i++) {           // V: 64 rows x 256B ([T,D])
                int c = tid + i * 256;
                int r = c >> 4, q16 = c & 15;
                cp16(so + FK_BYTES + (uint32_t)r * FQ_ROWB + (uint32_t)q16 * 16,
                     vb + (size_t)(kt * 64 + r) * Cc + q16 * 8);
            }
        }
        CP_COMMIT();
    };

    issueKV(0); issueKV(1);

    uint32_t qoff = sb + (uint32_t)((wr + (g8 & 1) * 8 + l8) * FQ_ROWB) + (uint32_t)(g8 >> 1) * 16;
    uint32_t koffB = (uint32_t)((((g8 >> 1) * 8 + l8)) * FQ_ROWB) + (uint32_t)(g8 & 1) * 16;
    // trans-ldsm V offset: row = k(t)-part, col = n(d)-part
    uint32_t voffB = (uint32_t)(((g8 & 1) * 8 + l8)) * FQ_ROWB + (uint32_t)((g8 >> 1) * 16);

    float Oa[16][4];
    #pragma unroll
    for (int j = 0; j < 16; j++)
        #pragma unroll
        for (int r = 0; r < 4; r++) Oa[j][r] = 0.f;
    float m0v = -1e30f, m1v = -1e30f, l0 = 0.f, l1 = 0.f;

    int grow0 = qt * 128 + wr + gid;
    int grow1 = grow0 + 8;
    const float ALPHA = 0.08838834764831843f;

    for (int kt = 0; kt < nkt; kt++) {
        CP_WAIT(1);
        __syncthreads();

        uint32_t stg = sb + FQ_BYTES + (uint32_t)(kt & 1) * FSTG;

        // S = Q K^T for this 64-col tile
        float S[8][4];
        #pragma unroll
        for (int j = 0; j < 8; j++) { S[j][0] = S[j][1] = S[j][2] = S[j][3] = 0.f; }
        #pragma unroll
        for (int ks = 0; ks < 8; ks++) {
            uint32_t aq[4];
            ldsm4(aq[0], aq[1], aq[2], aq[3], qoff + (uint32_t)ks * 32);
            uint32_t bk[8][2];
            #pragma unroll
            for (int jp = 0; jp < 4; jp++) {
                uint32_t t0, t1, t2, t3;
                ldsm4(t0, t1, t2, t3,
                      stg + koffB + (uint32_t)(jp * 16) * FQ_ROWB + (uint32_t)ks * 32);
                bk[2 * jp][0] = t0; bk[2 * jp][1] = t1;
                bk[2 * jp + 1][0] = t2; bk[2 * jp + 1][1] = t3;
            }
            #pragma unroll
            for (int j = 0; j < 8; j++) mma_f16(S[j], aq, bk[j]);
        }

        // mask + scale + online softmax
        int cbase = kt * 64;
        float mt0 = -1e30f, mt1 = -1e30f;
        #pragma unroll
        for (int j = 0; j < 8; j++) {
            int c0 = cbase + j * 8 + 2 * tig, c1 = c0 + 1;
            S[j][0] = (c0 <= grow0) ? S[j][0] * ALPHA : -1e30f;
            S[j][1] = (c1 <= grow0) ? S[j][1] * ALPHA : -1e30f;
            S[j][2] = (c0 <= grow1) ? S[j][2] * ALPHA : -1e30f;
            S[j][3] = (c1 <= grow1) ? S[j][3] * ALPHA : -1e30f;
            mt0 = fmaxf(mt0, fmaxf(S[j][0], S[j][1]));
            mt1 = fmaxf(mt1, fmaxf(S[j][2], S[j][3]));
        }
        mt0 = fmaxf(mt0, __shfl_xor_sync(0xffffffffu, mt0, 1));
        mt0 = fmaxf(mt0, __shfl_xor_sync(0xffffffffu, mt0, 2));
        mt1 = fmaxf(mt1, __shfl_xor_sync(0xffffffffu, mt1, 1));
        mt1 = fmaxf(mt1, __shfl_xor_sync(0xffffffffu, mt1, 2));
        float mn0 = fmaxf(m0v, mt0), mn1 = fmaxf(m1v, mt1);
        float f0 = __expf(m0v - mn0), f1 = __expf(m1v - mn1);
        m0v = mn0; m1v = mn1;
        float ps0 = 0.f, ps1 = 0.f;
        #pragma unroll
        for (int j = 0; j < 8; j++) {
            S[j][0] = __expf(S[j][0] - m0v);
            S[j][1] = __expf(S[j][1] - m0v);
            S[j][2] = __expf(S[j][2] - m1v);
            S[j][3] = __expf(S[j][3] - m1v);
            ps0 += S[j][0] + S[j][1];
            ps1 += S[j][2] + S[j][3];
        }
        ps0 += __shfl_xor_sync(0xffffffffu, ps0, 1);
        ps0 += __shfl_xor_sync(0xffffffffu, ps0, 2);
        ps1 += __shfl_xor_sync(0xffffffffu, ps1, 1);
        ps1 += __shfl_xor_sync(0xffffffffu, ps1, 2);
        l0 = l0 * f0 + ps0;
        l1 = l1 * f1 + ps1;
        #pragma unroll
        for (int j = 0; j < 16; j++) {
            Oa[j][0] *= f0; Oa[j][1] *= f0; Oa[j][2] *= f1; Oa[j][3] *= f1;
        }

        // O += P V : P (regs) x V tile (trans-ldmatrix on [t][d] rows)
        #pragma unroll
        for (int jj = 0; jj < 4; jj++) {
            uint32_t aP[4];
            __half2 p0 = __floats2half2_rn(S[2 * jj][0], S[2 * jj][1]);
            __half2 p1 = __floats2half2_rn(S[2 * jj][2], S[2 * jj][3]);
            __half2 p2 = __floats2half2_rn(S[2 * jj + 1][0], S[2 * jj + 1][1]);
            __half2 p3 = __floats2half2_rn(S[2 * jj + 1][2], S[2 * jj + 1][3]);
            aP[0] = *(uint32_t*)&p0; aP[1] = *(uint32_t*)&p1;
            aP[2] = *(uint32_t*)&p2; aP[3] = *(uint32_t*)&p3;
            uint32_t bv[16][2];
            #pragma unroll
            for (int jp = 0; jp < 8; jp++) {
                uint32_t t0, t1, t2, t3;
                ldsm4t(t0, t1, t2, t3,
                       stg + FK_BYTES + voffB + (uint32_t)(jj * 16) * FQ_ROWB + (uint32_t)(jp * 32));
                bv[2 * jp][0] = t0; bv[2 * jp][1] = t1;
                bv[2 * jp + 1][0] = t2; bv[2 * jp + 1][1] = t3;
            }
            #pragma unroll
            for (int dt = 0; dt < 16; dt++) mma_f16(Oa[dt], aP, bv[dt]);
        }

        __syncthreads();          // all warps done with stage (kt&1)
        issueKV(kt + 2);          // refill same buffer
    }

    float il0 = 1.f / l0, il1 = 1.f / l1;
    #pragma unroll
    for (int dt = 0; dt < 16; dt++) {
        int d = dt * 8 + 2 * tig;
        *(__half2*)(ob + (size_t)grow0 * Cc + d) = __floats2half2_rn(Oa[dt][0] * il0, Oa[dt][1] * il0);
        *(__half2*)(ob + (size_t)grow1 * Cc + d) = __floats2half2_rn(Oa[dt][2] * il1, Oa[dt][3] * il1);
    }
}

// ---------------------------------------------------------------------------
// Tiled transpose (fp32 -> fp16)
// ---------------------------------------------------------------------------
__global__ void transpose_f2h(const float* __restrict__ in, __half* __restrict__ out,
                              int ldi, int ldo, int zdiv,
                              long long iO, long long iI, long long oO, long long oI) {
    __shared__ float tile[32][33];
    long long z = blockIdx.z;
    in  += (z / zdiv) * iO + (z % zdiv) * iI;
    out += (z / zdiv) * oO + (z % zdiv) * oI;
    int r0 = blockIdx.y * 32, c0 = blockIdx.x * 32;
    int tx = threadIdx.x & 31, ty = threadIdx.x >> 5;
    #pragma unroll
    for (int i = ty; i < 32; i += 8)
        tile[i][tx] = in[(size_t)(r0 + i) * ldi + c0 + tx];
    __syncthreads();
    #pragma unroll
    for (int i = ty; i < 32; i += 8)
        out[(size_t)(c0 + i) * ldo + r0 + tx] = __float2half_rn(tile[tx][i]);
}

// ---------------------------------------------------------------------------
// Paired block reduction (two sums, one barrier tree)
// ---------------------------------------------------------------------------
__device__ __forceinline__ void blk_reduce_sum2(float& a, float& b) {
    __shared__ float2 sh[32];
    __syncthreads();
    int lane = threadIdx.x & 31, w = threadIdx.x >> 5;
    #pragma unroll
    for (int o = 16; o > 0; o >>= 1) {
        a += __shfl_down_sync(0xffffffffu, a, o);
        b += __shfl_down_sync(0xffffffffu, b, o);
    }
    if (lane == 0) sh[w] = make_float2(a, b);
    __syncthreads();
    int nw = blockDim.x >> 5;
    if (w == 0) {
        float2 v = (lane < nw) ? sh[lane] : make_float2(0.f, 0.f);
        a = v.x; b = v.y;
        #pragma unroll
        for (int o = 16; o > 0; o >>= 1) {
            a += __shfl_down_sync(0xffffffffu, a, o);
            b += __shfl_down_sync(0xffffffffu, b, o);
        }
        if (lane == 0) sh[0] = make_float2(a, b);
    }
    __syncthreads();
    float2 r = sh[0];
    a = r.x; b = r.y;
}

// ---------------------------------------------------------------------------
// LayerNorm: register-cached, float2 vectorized
// ---------------------------------------------------------------------------
__global__ void ln_kernel(const float* __restrict__ x, const float* __restrict__ g,
                          const float* __restrict__ b, __half* __restrict__ out) {
    size_t row = blockIdx.x;
    const float2* xr = (const float2*)(x + row * Cc);
    float2 xv[3];
    float s = 0.f, s2 = 0.f;
    #pragma unroll
    for (int j = 0; j < 3; j++) {
        xv[j] = xr[threadIdx.x + j * 256];
        s += xv[j].x + xv[j].y;
        s2 += xv[j].x * xv[j].x + xv[j].y * xv[j].y;
    }
    blk_reduce_sum2(s, s2);
    float mean = s * (1.0f / Cc);
    float var = s2 * (1.0f / Cc) - mean * mean;
    float inv = rsqrtf(var + EPSF);
    __half2* orow = (__half2*)(out + row * Cc);
    const float2* g2 = (const float2*)g;
    const float2* b2 = (const float2*)b;
    #pragma unroll
    for (int j = 0; j < 3; j++) {
        int idx = threadIdx.x + j * 256;
        float2 gg = g2[idx], bb = b2[idx];
        orow[idx] = __floats2half2_rn((xv[j].x - mean) * inv * gg.x + bb.x,
                                      (xv[j].y - mean) * inv * gg.y + bb.y);
    }
}

// ---------------------------------------------------------------------------
// Fused BN1 + LN2: register-cached, single x1 read
// ---------------------------------------------------------------------------
__global__ void bn_ln_kernel(const float* __restrict__ x1,
                             const float* __restrict__ bng, const float* __restrict__ bnb,
                             const float* __restrict__ lng, const float* __restrict__ lnb,
                             float* __restrict__ x2, __half* __restrict__ h) {
    int t = blockIdx.x;
    float2 xv[Bb][3];
    float s = 0.f, s2 = 0.f;
    #pragma unroll
    for (int bi = 0; bi < Bb; bi++) {
        const float2* xr = (const float2*)(x1 + ((size_t)bi * Tt + t) * Cc);
        #pragma unroll
        for (int j = 0; j < 3; j++) {
            xv[bi][j] = xr[threadIdx.x + j * 256];
            s += xv[bi][j].x + xv[bi][j].y;
            s2 += xv[bi][j].x * xv[bi][j].x + xv[bi][j].y * xv[bi][j].y;
        }
    }
    const float cnt = (float)(Bb * Cc);
    blk_reduce_sum2(s, s2);
    float mean = s / cnt;
    float var = s2 / cnt - mean * mean;
    float inv = rsqrtf(var + EPSF);
    float gg = bng[t], bv = bnb[t];

    const float2* lg2 = (const float2*)lng;
    const float2* lb2 = (const float2*)lnb;
    #pragma unroll
    for (int bi = 0; bi < Bb; bi++) {
        float2* x2r = (float2*)(x2 + ((size_t)bi * Tt + t) * Cc);
        __half2* hr = (__half2*)(h + ((size_t)bi * Tt + t) * Cc);
        float ls = 0.f, ls2 = 0.f;
        #pragma unroll
        for (int j = 0; j < 3; j++) {
            float yx = (xv[bi][j].x - mean) * inv * gg + bv;
            float yy = (xv[bi][j].y - mean) * inv * gg + bv;
            xv[bi][j] = make_float2(yx, yy);
            x2r[threadIdx.x + j * 256] = xv[bi][j];
            ls += yx + yy; ls2 += yx * yx + yy * yy;
        }
        blk_reduce_sum2(ls, ls2);
        float lm = ls * (1.0f / Cc);
        float lvar = ls2 * (1.0f / Cc) - lm * lm;
        float linv = rsqrtf(lvar + EPSF);
        #pragma unroll
        for (int j = 0; j < 3; j++) {
            int idx = threadIdx.x + j * 256;
            float2 lg = lg2[idx], lb = lb2[idx];
            hr[idx] = __floats2half2_rn((xv[bi][j].x - lm) * linv * lg.x + lb.x,
                                        (xv[bi][j].y - lm) * linv * lg.y + lb.y);
        }
    }
}

// ---------------------------------------------------------------------------
// Final BatchNorm: register-cached, single read
// ---------------------------------------------------------------------------
__global__ void bn_kernel(const float* __restrict__ x, const float* __restrict__ g,
                          const float* __restrict__ bb, float* __restrict__ out) {
    int t = blockIdx.x;
    float2 xv[Bb][3];
    float s = 0.f, s2 = 0.f;
    #pragma unroll
    for (int bi = 0; bi < Bb; bi++) {
        const float2* xr = (const float2*)(x + ((size_t)bi * Tt + t) * Cc);
        #pragma unroll
        for (int j = 0; j < 3; j++) {
            xv[bi][j] = xr[threadIdx.x + j * 256];
            s += xv[bi][j].x + xv[bi][j].y;
            s2 += xv[bi][j].x * xv[bi][j].x + xv[bi][j].y * xv[bi][j].y;
        }
    }
    const float cnt = (float)(Bb * Cc);
    blk_reduce_sum2(s, s2);
    float mean = s / cnt;
    float var = s2 / cnt - mean * mean;
    float inv = rsqrtf(var + EPSF);
    float gg = g[t], bv = bb[t];
    #pragma unroll
    for (int bi = 0; bi < Bb; bi++) {
        float2* orow = (float2*)(out + ((size_t)bi * Tt + t) * Cc);
        #pragma unroll
        for (int j = 0; j < 3; j++)
            orow[threadIdx.x + j * 256] =
                make_float2((xv[bi][j].x - mean) * inv * gg + bv,
                            (xv[bi][j].y - mean) * inv * gg + bv);
    }
}

// ---------------------------------------------------------------------------
// Launch
// ---------------------------------------------------------------------------
extern "C" void kernel_launch(void* const* d_in, const int* in_sizes, int n_in,
                              void* d_out, int out_size) {
    const float* x     = (const float*)d_in[0];
    const float* wq    = (const float*)d_in[1];
    const float* wk    = (const float*)d_in[2];
    const float* wv    = (const float*)d_in[3];
    const float* wo    = (const float*)d_in[4];
    const float* bo    = (const float*)d_in[5];
    const float* ln1_g = (const float*)d_in[6];
    const float* ln1_b = (const float*)d_in[7];
    const float* ln2_g = (const float*)d_in[8];
    const float* ln2_b = (const float*)d_in[9];
    const float* w1    = (const float*)d_in[10];
    const float* b1    = (const float*)d_in[11];
    const float* w2    = (const float*)d_in[12];
    const float* b2    = (const float*)d_in[13];
    const float* bn1_g = (const float*)d_in[14];
    const float* bn1_b = (const float*)d_in[15];
    const float* bn2_g = (const float*)d_in[16];
    const float* bn2_b = (const float*)d_in[17];
    float* out = (float*)d_out;

    __half *h, *qkv, *o, *f1, *wqkvT, *woT, *w1T, *w2T;
    float *x1, *x2, *f2;
    cudaGetSymbolAddress((void**)&h,   g_h);
    cudaGetSymbolAddress((void**)&qkv, g_qkv);
    cudaGetSymbolAddress((void**)&o,   g_o);
    cudaGetSymbolAddress((void**)&f1,  g_f1);
    cudaGetSymbolAddress((void**)&wqkvT, g_wqkvT);
    cudaGetSymbolAddress((void**)&woT, g_woT);
    cudaGetSymbolAddress((void**)&w1T, g_w1T);
    cudaGetSymbolAddress((void**)&w2T, g_w2T);
    cudaGetSymbolAddress((void**)&x1, g_x1);
    cudaGetSymbolAddress((void**)&x2, g_x2);
    cudaGetSymbolAddress((void**)&f2, g_f2);

    const long long CD = (long long)Cc * Dd;
    const long long HDC = (long long)Hh * Dd * Cc;

    const __half* q = qkv;
    const __half* k = qkv + (size_t)BT * Cc;
    const __half* v = qkv + (size_t)2 * BT * Cc;

    cudaFuncSetAttribute(hgemm, cudaFuncAttributeMaxDynamicSharedMemorySize, SMEM_BYTES);
    cudaFuncSetAttribute(flash_attn, cudaFuncAttributeMaxDynamicSharedMemorySize, FSMEM);

    transpose_f2h<<<dim3(Dd / 32, Cc / 32, Hh), 256>>>(wq, wqkvT,           Dd, Cc, 1, CD, 0, CD, 0);
    transpose_f2h<<<dim3(Dd / 32, Cc / 32, Hh), 256>>>(wk, wqkvT + HDC,     Dd, Cc, 1, CD, 0, CD, 0);
    transpose_f2h<<<dim3(Dd / 32, Cc / 32, Hh), 256>>>(wv, wqkvT + 2 * HDC, Dd, Cc, 1, CD, 0, CD, 0);
    ln_kernel<<<BT, 256>>>(x, ln1_g, ln1_b, h);
    transpose_f2h<<<dim3(Cc / 32, Cc / 32, 1), 256>>>(wo, woT, Cc, Cc, 1, 0, 0, 0, 0);

    // QKV fused: z = which*Hh + head
    {
        dim3 g(1, BT / 128, 3 * Hh);
        hgemm<<<g, 256, SMEM_BYTES>>>(h, wqkvT, (void*)qkv, BT, Dd, Cc, Cc, Cc, Cc, 1.f,
                                      nullptr, nullptr, 0, 1, Hh,
                                      0, 0, HDC, CD, (long long)BT * Cc, (long long)Dd);
    }

    transpose_f2h<<<dim3(Ff / 32, Cc / 32, 1), 256>>>(w1, w1T, Ff, Cc, 1, 0, 0, 0, 0);
    transpose_f2h<<<dim3(Cc / 32, Ff / 32, 1), 256>>>(w2, w2T, Cc, Ff, 1, 0, 0, 0, 0);

    // fused causal attention (V read directly)
    flash_attn<<<dim3(Tt / 128, Bb * Hh), 256, FSMEM>>>(q, k, v, o);

    // x1 = x + (O @ wo + bo)
    {
        dim3 g(Cc / 128, BT / 128, 1);
        hgemm<<<g, 256, SMEM_BYTES>>>(o, woT, x1, BT, Cc, Cc, Cc, Cc, Cc, 1.f,
                                      bo, x, 0, 0, 1, 0, 0, 0, 0, 0, 0);
    }

    // BN1 + LN2 fused
    bn_ln_kernel<<<Tt, 256>>>(x1, bn1_g, bn1_b, ln2_g, ln2_b, x2, h);

    // f1 = relu(h @ w1 + b1)
    {
        dim3 g(Ff / 128, BT / 128, 1);
        hgemm<<<g, 256, SMEM_BYTES>>>(h, w1T, (void*)f1, BT, Ff, Cc, Cc, Cc, Ff, 1.f,
                                      b1, nullptr, 1, 1, 1, 0, 0, 0, 0, 0, 0);
    }

    // f2 = x2 + (f1 @ w2 + b2)
    {
        dim3 g(Cc / 128, BT / 128, 1);
        hgemm<<<g, 256, SMEM_BYTES>>>(f1, w2T, f2, BT, Cc, Ff, Ff, Ff, Cc, 1.f,
                                      b2, x2, 0, 0, 1, 0, 0, 0, 0, 0, 0);
    }

    // bn2 -> out
    bn_kernel<<<Tt, 256>>>(f2, bn2_g, bn2_b, out);
}

// round 16
// speedup vs baseline: 1.5497x; 1.0073x over previous
#include <cuda_runtime.h>
#include <cuda_fp16.h>
#include <cstdint>

// Problem constants
#define Bb 8
#define Tt 1024
#define Cc 1536
#define Hh 12
#define Dd 128
#define Ff 6144          // 4*C
#define BT 8192          // B*T
#define EPSF 1e-5f

// hgemm pipeline: 4 stages, K-chunk 32 (R12-proven)
#define STG_BYTES 20480
#define SMEM_BYTES (4 * STG_BYTES)   // 81920

// flash-attn smem (2-stage, V read directly in [T,D] layout)
#define FQ_ROWB 272u                  // 128 halves + pad
#define FQ_BYTES (128u * FQ_ROWB)     // 34816
#define FK_BYTES (64u * FQ_ROWB)      // 17408 (K tile: 64 rows x 256B)
#define FV_BYTES (64u * FQ_ROWB)      // 17408 (V tile: 64 rows x 256B)
#define FSTG (FK_BYTES + FV_BYTES)    // 34816
#define FSMEM (FQ_BYTES + 2u * FSTG)  // 104448 -> 2 CTAs/SM

// ---------------------------------------------------------------------------
// Scratch
// ---------------------------------------------------------------------------
__device__ __align__(256) __half g_h   [(size_t)BT * Cc];
__device__ __align__(256) __half g_qkv [(size_t)3 * BT * Cc];
__device__ __align__(256) __half g_o   [(size_t)BT * Cc];
__device__ __align__(256) __half g_f1  [(size_t)BT * Ff];
__device__ __align__(256) __half g_wqkvT[(size_t)3 * Hh * Dd * Cc];
__device__ __align__(256) __half g_woT [(size_t)Cc * Cc];
__device__ __align__(256) __half g_w1T [(size_t)Ff * Cc];
__device__ __align__(256) __half g_w2T [(size_t)Cc * Ff];
__device__ __align__(256) __half g_x2h [(size_t)BT * Cc];   // fp16 residual copy
__device__ float g_x1 [(size_t)BT * Cc];
__device__ float g_f2 [(size_t)BT * Cc];

// ---------------------------------------------------------------------------
// Baseline-PTX helpers
// ---------------------------------------------------------------------------
__device__ __forceinline__ uint32_t smem_u32(const void* p) {
    uint32_t a;
    asm("{ .reg .u64 t; cvta.to.shared.u64 t, %1; cvt.u32.u64 %0, t; }" : "=r"(a) : "l"(p));
    return a;
}
__device__ __forceinline__ void cp16(uint32_t saddr, const void* gptr) {
    asm volatile("cp.async.cg.shared.global [%0], [%1], 16;" :: "r"(saddr), "l"(gptr));
}
#define CP_COMMIT() asm volatile("cp.async.commit_group;" ::: "memory")
#define CP_WAIT(n)  asm volatile("cp.async.wait_group %0;" :: "n"(n) : "memory")

__device__ __forceinline__ void ldsm4(uint32_t& r0, uint32_t& r1, uint32_t& r2,
                                      uint32_t& r3, uint32_t addr) {
    asm volatile("ldmatrix.sync.aligned.m8n8.x4.shared.b16 {%0,%1,%2,%3}, [%4];"
                 : "=r"(r0), "=r"(r1), "=r"(r2), "=r"(r3) : "r"(addr));
}
__device__ __forceinline__ void ldsm4t(uint32_t& r0, uint32_t& r1, uint32_t& r2,
                                       uint32_t& r3, uint32_t addr) {
    asm volatile("ldmatrix.sync.aligned.m8n8.x4.trans.shared.b16 {%0,%1,%2,%3}, [%4];"
                 : "=r"(r0), "=r"(r1), "=r"(r2), "=r"(r3) : "r"(addr));
}
__device__ __forceinline__ void mma_f16(float* c, const uint32_t* a, const uint32_t* b) {
    asm volatile(
        "mma.sync.aligned.m16n8k16.row.col.f32.f16.f16.f32 "
        "{%0,%1,%2,%3}, {%4,%5,%6,%7}, {%8,%9}, {%0,%1,%2,%3};"
        : "+f"(c[0]), "+f"(c[1]), "+f"(c[2]), "+f"(c[3])
        : "r"(a[0]), "r"(a[1]), "r"(a[2]), "r"(a[3]), "r"(b[0]), "r"(b[1]));
}

// ---------------------------------------------------------------------------
// fp16 NT GEMM (R12-proven): CTA 128x128, 8 warps (4Mx2N), K chunk 32, 4-stage.
// addp may be fp32 (addHalf=0) or fp16 (addHalf=1).
// ---------------------------------------------------------------------------
__global__ __launch_bounds__(256, 2)
void hgemm(const __half* __restrict__ A, const __half* __restrict__ Bm,
           void* __restrict__ Cv, int M, int N, int K,
           int lda, int ldb, int ldc, float alpha,
           const float* __restrict__ bias, const void* __restrict__ addp,
           int addHalf, int doRelu, int outHalf, int zdiv,
           long long aO, long long aI, long long bO, long long bI,
           long long cO, long long cI) {
    int m0 = blockIdx.y * 128, n0 = blockIdx.x * 128;

    long long z = blockIdx.z;
    long long zo = z / zdiv, zi = z % zdiv;
    A  += zo * aO + zi * aI;
    Bm += zo * bO + zi * bI;
    size_t coff = (size_t)(zo * cO + zi * cI);

    extern __shared__ __align__(16) char sm[];
    uint32_t sbase = smem_u32(sm);

    int tid = threadIdx.x, wid = tid >> 5, lane = tid & 31;
    int gid = lane >> 2, tig = lane & 3;
    int wm = (wid & 3) * 32, wn = (wid >> 2) * 64;

    int lrow = tid >> 1, lsel = tid & 1;
    const __half* aR = A + (size_t)(m0 + lrow) * lda + lsel * 16;
    const __half* bR = Bm + (size_t)(n0 + lrow) * ldb + lsel * 16;
    uint32_t dA = sbase + (uint32_t)(lrow * 80 + lsel * 32);
    uint32_t dB = dA + 10240u;

    int nch = K >> 5;
    auto issue = [&](int ch) {
        if (ch < nch) {
            uint32_t so = (uint32_t)(ch & 3) * STG_BYTES;
            int k0 = ch * 32;
            cp16(dA + so,      aR + k0);
            cp16(dA + so + 16, aR + k0 + 8);
            cp16(dB + so,      bR + k0);
            cp16(dB + so + 16, bR + k0 + 8);
        }
        CP_COMMIT();
    };

    int g8 = lane >> 3, l8 = lane & 7;
    uint32_t aoff = (uint32_t)((((g8 & 1) * 8 + l8) * 80) + (g8 >> 1) * 16);
    uint32_t boff = 10240u + (uint32_t)((((g8 >> 1) * 8 + l8) * 80) + (g8 & 1) * 16);

    float acc[2][8][4];
    #pragma unroll
    for (int i = 0; i < 2; i++)
        #pragma unroll
        for (int j = 0; j < 8; j++)
            #pragma unroll
            for (int r = 0; r < 4; r++) acc[i][j][r] = 0.f;

    issue(0); issue(1); issue(2);

    for (int ch = 0; ch < nch; ch++) {
        CP_WAIT(2);
        __syncthreads();
        issue(ch + 3);

        uint32_t stg = sbase + (uint32_t)(ch & 3) * STG_BYTES;
        uint32_t aw0 = stg + aoff + (uint32_t)(wm * 80);
        uint32_t aw1 = aw0 + 16u * 80u;
        uint32_t bw  = stg + boff + (uint32_t)(wn * 80);

        #pragma unroll
        for (int s = 0; s < 2; s++) {
            uint32_t a[2][4];
            ldsm4(a[0][0], a[0][1], a[0][2], a[0][3], aw0 + s * 32);
            ldsm4(a[1][0], a[1][1], a[1][2], a[1][3], aw1 + s * 32);
            uint32_t b[8][2];
            #pragma unroll
            for (int jj = 0; jj < 4; jj++) {
                uint32_t t0, t1, t2, t3;
                ldsm4(t0, t1, t2, t3, bw + (uint32_t)(jj * 16 * 80) + s * 32);
                b[2 * jj][0] = t0; b[2 * jj][1] = t1;
                b[2 * jj + 1][0] = t2; b[2 * jj + 1][1] = t3;
            }
            #pragma unroll
            for (int i = 0; i < 2; i++)
                #pragma unroll
                for (int j = 0; j < 8; j++)
                    mma_f16(acc[i][j], a[i], b[j]);
        }
    }

    #pragma unroll
    for (int i = 0; i < 2; i++) {
        #pragma unroll
        for (int j = 0; j < 8; j++) {
            int r0 = m0 + wm + i * 16 + gid;
            int c  = n0 + wn + j * 8 + 2 * tig;
            #pragma unroll
            for (int hh = 0; hh < 2; hh++) {
                int r = r0 + hh * 8;
                float v0 = acc[i][j][2 * hh + 0] * alpha;
                float v1 = acc[i][j][2 * hh + 1] * alpha;
                if (bias) { v0 += bias[c]; v1 += bias[c + 1]; }
                if (doRelu) { v0 = fmaxf(v0, 0.f); v1 = fmaxf(v1, 0.f); }
                if (addp) {
                    size_t aidx = coff + (size_t)r * ldc + c;
                    if (addHalf) {
                        __half2 a2 = *(const __half2*)((const __half*)addp + aidx);
                        v0 += __low2float(a2); v1 += __high2float(a2);
                    } else {
                        const float* ap = (const float*)addp + aidx;
                        v0 += ap[0]; v1 += ap[1];
                    }
                }
                if (outHalf) {
                    __half2* cp = (__half2*)((__half*)Cv + coff + (size_t)r * ldc + c);
                    *cp = __floats2half2_rn(v0, v1);
                } else {
                    float2* cp = (float2*)((float*)Cv + coff + (size_t)r * ldc + c);
                    *cp = make_float2(v0, v1);
                }
            }
        }
    }
}

// ---------------------------------------------------------------------------
// Fused flash attention: V read directly from [B,T,C] via trans-ldmatrix.
// 2-stage pipeline, 2 CTAs/SM, heavy tiles first.
// ---------------------------------------------------------------------------
__global__ __launch_bounds__(256, 2)
void flash_attn(const __half* __restrict__ qg, const __half* __restrict__ kg,
                const __half* __restrict__ vg, __half* __restrict__ og) {
    extern __shared__ __align__(16) char sm[];
    uint32_t sb = smem_u32(sm);
    int qt = gridDim.x - 1 - blockIdx.x;    // heavy (large-qt) tiles first
    int z = blockIdx.y;
    int bi = z / Hh, hi = z % Hh;
    const __half* qb = qg + (size_t)bi * Tt * Cc + hi * Dd;
    const __half* kb = kg + (size_t)bi * Tt * Cc + hi * Dd;
    const __half* vb = vg + (size_t)bi * Tt * Cc + hi * Dd;
    __half* ob = og + (size_t)bi * Tt * Cc + hi * Dd;

    int tid = threadIdx.x, wid = tid >> 5, lane = tid & 31;
    int gid = lane >> 2, tig = lane & 3;
    int g8 = lane >> 3, l8 = lane & 7;
    int wr = wid * 16;
    int nkt = 2 * qt + 2;

    // Q tile once (bundled into first commit group)
    #pragma unroll
    for (int i = 0; i < 8; i++) {
        int c = tid + i * 256;
        int r = c >> 4, q16 = c & 15;
        cp16(sb + (uint32_t)r * FQ_ROWB + (uint32_t)q16 * 16,
             qb + (size_t)(qt * 128 + r) * Cc + q16 * 8);
    }
    auto issueKV = [&](int kt) {
        if (kt < nkt) {
            uint32_t so = sb + FQ_BYTES + (uint32_t)(kt & 1) * FSTG;
            #pragma unroll
            for (int i = 0; i < 4; i++) {           // K: 64 rows x 256B
                int c = tid + i * 256;
                int r = c >> 4, q16 = c & 15;
                cp16(so + (uint32_t)r * FQ_ROWB + (uint32_t)q16 * 16,
                     kb + (size_t)(kt * 64 + r) * Cc + q16 * 8);
            }
            #pragma unroll
            for (int i = 0; i < 4; i++) {           // V: 64 rows x 256B ([T,D])
                int c = tid + i * 256;
                int r = c >> 4, q16 = c & 15;
                cp16(so + FK_BYTES + (uint32_t)r * FQ_ROWB + (uint32_t)q16 * 16,
                     vb + (size_t)(kt * 64 + r) * Cc + q16 * 8);
            }
        }
        CP_COMMIT();
    };

    issueKV(0); issueKV(1);

    uint32_t qoff = sb + (uint32_t)((wr + (g8 & 1) * 8 + l8) * FQ_ROWB) + (uint32_t)(g8 >> 1) * 16;
    uint32_t koffB = (uint32_t)((((g8 >> 1) * 8 + l8)) * FQ_ROWB) + (uint32_t)(g8 & 1) * 16;
    // trans-ldsm V offset: row = k(t)-part, col = n(d)-part
    uint32_t voffB = (uint32_t)(((g8 & 1) * 8 + l8)) * FQ_ROWB + (uint32_t)((g8 >> 1) * 16);

    float Oa[16][4];
    #pragma unroll
    for (int j = 0; j < 16; j++)
        #pragma unroll
        for (int r = 0; r < 4; r++) Oa[j][r] = 0.f;
    float m0v = -1e30f, m1v = -1e30f, l0 = 0.f, l1 = 0.f;

    int grow0 = qt * 128 + wr + gid;
    int grow1 = grow0 + 8;
    const float ALPHA = 0.08838834764831843f;

    for (int kt = 0; kt < nkt; kt++) {
        CP_WAIT(1);
        __syncthreads();

        uint32_t stg = sb + FQ_BYTES + (uint32_t)(kt & 1) * FSTG;

        // S = Q K^T for this 64-col tile
        float S[8][4];
        #pragma unroll
        for (int j = 0; j < 8; j++) { S[j][0] = S[j][1] = S[j][2] = S[j][3] = 0.f; }
        #pragma unroll
        for (int ks = 0; ks < 8; ks++) {
            uint32_t aq[4];
            ldsm4(aq[0], aq[1], aq[2], aq[3], qoff + (uint32_t)ks * 32);
            uint32_t bk[8][2];
            #pragma unroll
            for (int jp = 0; jp < 4; jp++) {
                uint32_t t0, t1, t2, t3;
                ldsm4(t0, t1, t2, t3,
                      stg + koffB + (uint32_t)(jp * 16) * FQ_ROWB + (uint32_t)ks * 32);
                bk[2 * jp][0] = t0; bk[2 * jp][1] = t1;
                bk[2 * jp + 1][0] = t2; bk[2 * jp + 1][1] = t3;
            }
            #pragma unroll
            for (int j = 0; j < 8; j++) mma_f16(S[j], aq, bk[j]);
        }

        // mask + scale + online softmax
        int cbase = kt * 64;
        float mt0 = -1e30f, mt1 = -1e30f;
        #pragma unroll
        for (int j = 0; j < 8; j++) {
            int c0 = cbase + j * 8 + 2 * tig, c1 = c0 + 1;
            S[j][0] = (c0 <= grow0) ? S[j][0] * ALPHA : -1e30f;
            S[j][1] = (c1 <= grow0) ? S[j][1] * ALPHA : -1e30f;
            S[j][2] = (c0 <= grow1) ? S[j][2] * ALPHA : -1e30f;
            S[j][3] = (c1 <= grow1) ? S[j][3] * ALPHA : -1e30f;
            mt0 = fmaxf(mt0, fmaxf(S[j][0], S[j][1]));
            mt1 = fmaxf(mt1, fmaxf(S[j][2], S[j][3]));
        }
        mt0 = fmaxf(mt0, __shfl_xor_sync(0xffffffffu, mt0, 1));
        mt0 = fmaxf(mt0, __shfl_xor_sync(0xffffffffu, mt0, 2));
        mt1 = fmaxf(mt1, __shfl_xor_sync(0xffffffffu, mt1, 1));
        mt1 = fmaxf(mt1, __shfl_xor_sync(0xffffffffu, mt1, 2));
        float mn0 = fmaxf(m0v, mt0), mn1 = fmaxf(m1v, mt1);
        float f0 = __expf(m0v - mn0), f1 = __expf(m1v - mn1);
        m0v = mn0; m1v = mn1;
        float ps0 = 0.f, ps1 = 0.f;
        #pragma unroll
        for (int j = 0; j < 8; j++) {
            S[j][0] = __expf(S[j][0] - m0v);
            S[j][1] = __expf(S[j][1] - m0v);
            S[j][2] = __expf(S[j][2] - m1v);
            S[j][3] = __expf(S[j][3] - m1v);
            ps0 += S[j][0] + S[j][1];
            ps1 += S[j][2] + S[j][3];
        }
        ps0 += __shfl_xor_sync(0xffffffffu, ps0, 1);
        ps0 += __shfl_xor_sync(0xffffffffu, ps0, 2);
        ps1 += __shfl_xor_sync(0xffffffffu, ps1, 1);
        ps1 += __shfl_xor_sync(0xffffffffu, ps1, 2);
        l0 = l0 * f0 + ps0;
        l1 = l1 * f1 + ps1;
        #pragma unroll
        for (int j = 0; j < 16; j++) {
            Oa[j][0] *= f0; Oa[j][1] *= f0; Oa[j][2] *= f1; Oa[j][3] *= f1;
        }

        // O += P V : P (regs) x V tile (trans-ldmatrix on [t][d] rows)
        #pragma unroll
        for (int jj = 0; jj < 4; jj++) {
            uint32_t aP[4];
            __half2 p0 = __floats2half2_rn(S[2 * jj][0], S[2 * jj][1]);
            __half2 p1 = __floats2half2_rn(S[2 * jj][2], S[2 * jj][3]);
            __half2 p2 = __floats2half2_rn(S[2 * jj + 1][0], S[2 * jj + 1][1]);
            __half2 p3 = __floats2half2_rn(S[2 * jj + 1][2], S[2 * jj + 1][3]);
            aP[0] = *(uint32_t*)&p0; aP[1] = *(uint32_t*)&p1;
            aP[2] = *(uint32_t*)&p2; aP[3] = *(uint32_t*)&p3;
            uint32_t bv[16][2];
            #pragma unroll
            for (int jp = 0; jp < 8; jp++) {
                uint32_t t0, t1, t2, t3;
                ldsm4t(t0, t1, t2, t3,
                       stg + FK_BYTES + voffB + (uint32_t)(jj * 16) * FQ_ROWB + (uint32_t)(jp * 32));
                bv[2 * jp][0] = t0; bv[2 * jp][1] = t1;
                bv[2 * jp + 1][0] = t2; bv[2 * jp + 1][1] = t3;
            }
            #pragma unroll
            for (int dt = 0; dt < 16; dt++) mma_f16(Oa[dt], aP, bv[dt]);
        }

        __syncthreads();          // all warps done with stage (kt&1)
        issueKV(kt + 2);          // refill same buffer
    }

    float il0 = 1.f / l0, il1 = 1.f / l1;
    #pragma unroll
    for (int dt = 0; dt < 16; dt++) {
        int d = dt * 8 + 2 * tig;
        *(__half2*)(ob + (size_t)grow0 * Cc + d) = __floats2half2_rn(Oa[dt][0] * il0, Oa[dt][1] * il0);
        *(__half2*)(ob + (size_t)grow1 * Cc + d) = __floats2half2_rn(Oa[dt][2] * il1, Oa[dt][3] * il1);
    }
}

// ---------------------------------------------------------------------------
// Tiled transpose (fp32 -> fp16)
// ---------------------------------------------------------------------------
__global__ void transpose_f2h(const float* __restrict__ in, __half* __restrict__ out,
                              int ldi, int ldo, int zdiv,
                              long long iO, long long iI, long long oO, long long oI) {
    __shared__ float tile[32][33];
    long long z = blockIdx.z;
    in  += (z / zdiv) * iO + (z % zdiv) * iI;
    out += (z / zdiv) * oO + (z % zdiv) * oI;
    int r0 = blockIdx.y * 32, c0 = blockIdx.x * 32;
    int tx = threadIdx.x & 31, ty = threadIdx.x >> 5;
    #pragma unroll
    for (int i = ty; i < 32; i += 8)
        tile[i][tx] = in[(size_t)(r0 + i) * ldi + c0 + tx];
    __syncthreads();
    #pragma unroll
    for (int i = ty; i < 32; i += 8)
        out[(size_t)(c0 + i) * ldo + r0 + tx] = __float2half_rn(tile[tx][i]);
}

// Fused QKV weight transpose: z = which*Hh + head; in (C,D) per head -> out (D,C)
__global__ void transpose_qkv(const float* __restrict__ wq, const float* __restrict__ wk,
                              const float* __restrict__ wv, __half* __restrict__ out) {
    __shared__ float tile[32][33];
    long long z = blockIdx.z;
    int which = (int)(z / Hh), head = (int)(z % Hh);
    const float* in = (which == 0 ? wq : which == 1 ? wk : wv) + (size_t)head * Cc * Dd;
    __half* o = out + ((size_t)which * Hh + head) * (size_t)Dd * Cc;
    int r0 = blockIdx.y * 32, c0 = blockIdx.x * 32;
    int tx = threadIdx.x & 31, ty = threadIdx.x >> 5;
    #pragma unroll
    for (int i = ty; i < 32; i += 8)
        tile[i][tx] = in[(size_t)(r0 + i) * Dd + c0 + tx];
    __syncthreads();
    #pragma unroll
    for (int i = ty; i < 32; i += 8)
        o[(size_t)(c0 + i) * Cc + r0 + tx] = __float2half_rn(tile[tx][i]);
}

// ---------------------------------------------------------------------------
// Paired block reduction (two sums, one barrier tree)
// ---------------------------------------------------------------------------
__device__ __forceinline__ void blk_reduce_sum2(float& a, float& b) {
    __shared__ float2 sh[32];
    __syncthreads();
    int lane = threadIdx.x & 31, w = threadIdx.x >> 5;
    #pragma unroll
    for (int o = 16; o > 0; o >>= 1) {
        a += __shfl_down_sync(0xffffffffu, a, o);
        b += __shfl_down_sync(0xffffffffu, b, o);
    }
    if (lane == 0) sh[w] = make_float2(a, b);
    __syncthreads();
    int nw = blockDim.x >> 5;
    if (w == 0) {
        float2 v = (lane < nw) ? sh[lane] : make_float2(0.f, 0.f);
        a = v.x; b = v.y;
        #pragma unroll
        for (int o = 16; o > 0; o >>= 1) {
            a += __shfl_down_sync(0xffffffffu, a, o);
            b += __shfl_down_sync(0xffffffffu, b, o);
        }
        if (lane == 0) sh[0] = make_float2(a, b);
    }
    __syncthreads();
    float2 r = sh[0];
    a = r.x; b = r.y;
}

// ---------------------------------------------------------------------------
// LayerNorm: register-cached, float2 vectorized
// ---------------------------------------------------------------------------
__global__ void ln_kernel(const float* __restrict__ x, const float* __restrict__ g,
                          const float* __restrict__ b, __half* __restrict__ out) {
    size_t row = blockIdx.x;
    const float2* xr = (const float2*)(x + row * Cc);
    float2 xv[3];
    float s = 0.f, s2 = 0.f;
    #pragma unroll
    for (int j = 0; j < 3; j++) {
        xv[j] = xr[threadIdx.x + j * 256];
        s += xv[j].x + xv[j].y;
        s2 += xv[j].x * xv[j].x + xv[j].y * xv[j].y;
    }
    blk_reduce_sum2(s, s2);
    float mean = s * (1.0f / Cc);
    float var = s2 * (1.0f / Cc) - mean * mean;
    float inv = rsqrtf(var + EPSF);
    __half2* orow = (__half2*)(out + row * Cc);
    const float2* g2 = (const float2*)g;
    const float2* b2 = (const float2*)b;
    #pragma unroll
    for (int j = 0; j < 3; j++) {
        int idx = threadIdx.x + j * 256;
        float2 gg = g2[idx], bb = b2[idx];
        orow[idx] = __floats2half2_rn((xv[j].x - mean) * inv * gg.x + bb.x,
                                      (xv[j].y - mean) * inv * gg.y + bb.y);
    }
}

// ---------------------------------------------------------------------------
// Fused BN1 + LN2: register-cached, single x1 read. LN2 math in fp32;
// residual copy x2 stored fp16.
// ---------------------------------------------------------------------------
__global__ void bn_ln_kernel(const float* __restrict__ x1,
                             const float* __restrict__ bng, const float* __restrict__ bnb,
                             const float* __restrict__ lng, const float* __restrict__ lnb,
                             __half* __restrict__ x2h, __half* __restrict__ h) {
    int t = blockIdx.x;
    float2 xv[Bb][3];
    float s = 0.f, s2 = 0.f;
    #pragma unroll
    for (int bi = 0; bi < Bb; bi++) {
        const float2* xr = (const float2*)(x1 + ((size_t)bi * Tt + t) * Cc);
        #pragma unroll
        for (int j = 0; j < 3; j++) {
            xv[bi][j] = xr[threadIdx.x + j * 256];
            s += xv[bi][j].x + xv[bi][j].y;
            s2 += xv[bi][j].x * xv[bi][j].x + xv[bi][j].y * xv[bi][j].y;
        }
    }
    const float cnt = (float)(Bb * Cc);
    blk_reduce_sum2(s, s2);
    float mean = s / cnt;
    float var = s2 / cnt - mean * mean;
    float inv = rsqrtf(var + EPSF);
    float gg = bng[t], bv = bnb[t];

    const float2* lg2 = (const float2*)lng;
    const float2* lb2 = (const float2*)lnb;
    #pragma unroll
    for (int bi = 0; bi < Bb; bi++) {
        __half2* x2r = (__half2*)(x2h + ((size_t)bi * Tt + t) * Cc);
        __half2* hr = (__half2*)(h + ((size_t)bi * Tt + t) * Cc);
        float ls = 0.f, ls2 = 0.f;
        #pragma unroll
        for (int j = 0; j < 3; j++) {
            float yx = (xv[bi][j].x - mean) * inv * gg + bv;
            float yy = (xv[bi][j].y - mean) * inv * gg + bv;
            xv[bi][j] = make_float2(yx, yy);
            x2r[threadIdx.x + j * 256] = __floats2half2_rn(yx, yy);
            ls += yx + yy; ls2 += yx * yx + yy * yy;
        }
        blk_reduce_sum2(ls, ls2);
        float lm = ls * (1.0f / Cc);
        float lvar = ls2 * (1.0f / Cc) - lm * lm;
        float linv = rsqrtf(lvar + EPSF);
        #pragma unroll
        for (int j = 0; j < 3; j++) {
            int idx = threadIdx.x + j * 256;
            float2 lg = lg2[idx], lb = lb2[idx];
            hr[idx] = __floats2half2_rn((xv[bi][j].x - lm) * linv * lg.x + lb.x,
                                        (xv[bi][j].y - lm) * linv * lg.y + lb.y);
        }
    }
}

// ---------------------------------------------------------------------------
// Final BatchNorm: register-cached, single read
// ---------------------------------------------------------------------------
__global__ void bn_kernel(const float* __restrict__ x, const float* __restrict__ g,
                          const float* __restrict__ bb, float* __restrict__ out) {
    int t = blockIdx.x;
    float2 xv[Bb][3];
    float s = 0.f, s2 = 0.f;
    #pragma unroll
    for (int bi = 0; bi < Bb; bi++) {
        const float2* xr = (const float2*)(x + ((size_t)bi * Tt + t) * Cc);
        #pragma unroll
        for (int j = 0; j < 3; j++) {
            xv[bi][j] = xr[threadIdx.x + j * 256];
            s += xv[bi][j].x + xv[bi][j].y;
            s2 += xv[bi][j].x * xv[bi][j].x + xv[bi][j].y * xv[bi][j].y;
        }
    }
    const float cnt = (float)(Bb * Cc);
    blk_reduce_sum2(s, s2);
    float mean = s / cnt;
    float var = s2 / cnt - mean * mean;
    float inv = rsqrtf(var + EPSF);
    float gg = g[t], bv = bb[t];
    #pragma unroll
    for (int bi = 0; bi < Bb; bi++) {
        float2* orow = (float2*)(out + ((size_t)bi * Tt + t) * Cc);
        #pragma unroll
        for (int j = 0; j < 3; j++)
            orow[threadIdx.x + j * 256] =
                make_float2((xv[bi][j].x - mean) * inv * gg + bv,
                            (xv[bi][j].y - mean) * inv * gg + bv);
    }
}

// ---------------------------------------------------------------------------
// Launch
// ---------------------------------------------------------------------------
extern "C" void kernel_launch(void* const* d_in, const int* in_sizes, int n_in,
                              void* d_out, int out_size) {
    const float* x     = (const float*)d_in[0];
    const float* wq    = (const float*)d_in[1];
    const float* wk    = (const float*)d_in[2];
    const float* wv    = (const float*)d_in[3];
    const float* wo    = (const float*)d_in[4];
    const float* bo    = (const float*)d_in[5];
    const float* ln1_g = (const float*)d_in[6];
    const float* ln1_b = (const float*)d_in[7];
    const float* ln2_g = (const float*)d_in[8];
    const float* ln2_b = (const float*)d_in[9];
    const float* w1    = (const float*)d_in[10];
    const float* b1    = (const float*)d_in[11];
    const float* w2    = (const float*)d_in[12];
    const float* b2    = (const float*)d_in[13];
    const float* bn1_g = (const float*)d_in[14];
    const float* bn1_b = (const float*)d_in[15];
    const float* bn2_g = (const float*)d_in[16];
    const float* bn2_b = (const float*)d_in[17];
    float* out = (float*)d_out;

    __half *h, *qkv, *o, *f1, *wqkvT, *woT, *w1T, *w2T, *x2h;
    float *x1, *f2;
    cudaGetSymbolAddress((void**)&h,   g_h);
    cudaGetSymbolAddress((void**)&qkv, g_qkv);
    cudaGetSymbolAddress((void**)&o,   g_o);
    cudaGetSymbolAddress((void**)&f1,  g_f1);
    cudaGetSymbolAddress((void**)&wqkvT, g_wqkvT);
    cudaGetSymbolAddress((void**)&woT, g_woT);
    cudaGetSymbolAddress((void**)&w1T, g_w1T);
    cudaGetSymbolAddress((void**)&w2T, g_w2T);
    cudaGetSymbolAddress((void**)&x2h, g_x2h);
    cudaGetSymbolAddress((void**)&x1, g_x1);
    cudaGetSymbolAddress((void**)&f2, g_f2);

    const long long CD = (long long)Cc * Dd;
    const long long HDC = (long long)Hh * Dd * Cc;

    const __half* q = qkv;
    const __half* k = qkv + (size_t)BT * Cc;
    const __half* v = qkv + (size_t)2 * BT * Cc;

    cudaFuncSetAttribute(hgemm, cudaFuncAttributeMaxDynamicSharedMemorySize, SMEM_BYTES);
    cudaFuncSetAttribute(flash_attn, cudaFuncAttributeMaxDynamicSharedMemorySize, FSMEM);

    transpose_qkv<<<dim3(Dd / 32, Cc / 32, 3 * Hh), 256>>>(wq, wk, wv, wqkvT);
    ln_kernel<<<BT, 256>>>(x, ln1_g, ln1_b, h);
    transpose_f2h<<<dim3(Cc / 32, Cc / 32, 1), 256>>>(wo, woT, Cc, Cc, 1, 0, 0, 0, 0);

    // QKV fused: z = which*Hh + head
    {
        dim3 g(1, BT / 128, 3 * Hh);
        hgemm<<<g, 256, SMEM_BYTES>>>(h, wqkvT, (void*)qkv, BT, Dd, Cc, Cc, Cc, Cc, 1.f,
                                      nullptr, nullptr, 0, 0, 1, Hh,
                                      0, 0, HDC, CD, (long long)BT * Cc, (long long)Dd);
    }

    transpose_f2h<<<dim3(Ff / 32, Cc / 32, 1), 256>>>(w1, w1T, Ff, Cc, 1, 0, 0, 0, 0);
    transpose_f2h<<<dim3(Cc / 32, Ff / 32, 1), 256>>>(w2, w2T, Cc, Ff, 1, 0, 0, 0, 0);

    // fused causal attention (V read directly)
    flash_attn<<<dim3(Tt / 128, Bb * Hh), 256, FSMEM>>>(q, k, v, o);

    // x1 = x + (O @ wo + bo)
    {
        dim3 g(Cc / 128, BT / 128, 1);
        hgemm<<<g, 256, SMEM_BYTES>>>(o, woT, x1, BT, Cc, Cc, Cc, Cc, Cc, 1.f,
                                      bo, x, 0, 0, 0, 1, 0, 0, 0, 0, 0, 0);
    }

    // BN1 + LN2 fused -> x2h (fp16), h (fp16)
    bn_ln_kernel<<<Tt, 256>>>(x1, bn1_g, bn1_b, ln2_g, ln2_b, x2h, h);

    // f1 = relu(h @ w1 + b1)
    {
        dim3 g(Ff / 128, BT / 128, 1);
        hgemm<<<g, 256, SMEM_BYTES>>>(h, w1T, (void*)f1, BT, Ff, Cc, Cc, Cc, Ff, 1.f,
                                      b1, nullptr, 0, 1, 1, 1, 0, 0, 0, 0, 0, 0);
    }

    // f2 = x2 + (f1 @ w2 + b2)   (x2 read as fp16)
    {
        dim3 g(Cc / 128, BT / 128, 1);
        hgemm<<<g, 256, SMEM_BYTES>>>(f1, w2T, f2, BT, Cc, Ff, Ff, Ff, Cc, 1.f,
                                      b2, x2h, 1, 0, 0, 1, 0, 0, 0, 0, 0, 0);
    }

    // bn2 -> out
    bn_kernel<<<Tt, 256>>>(f2, bn2_g, bn2_b, out);
}